// round 14
// baseline (speedup 1.0000x reference)
#include <cuda_runtime.h>
#include <cstdint>

// ---------------- problem constants ----------------
#define SEQA   4096
#define BATCH  8
#define DM     1024
#define NHEADS 16
#define HD     64
#define MROWS  (SEQA*BATCH)   // 32768

// ---------------- scratch (device globals; no allocation allowed) ----------
__device__ float g_Q[(size_t)MROWS * DM];
__device__ float g_K[(size_t)MROWS * DM];
__device__ float g_V[(size_t)MROWS * DM];
__device__ float g_X[(size_t)MROWS * DM];

// ---------------- helpers ----------------
__device__ __forceinline__ uint32_t f2tf32(float f) {
    uint32_t u;
    asm("cvt.rna.tf32.f32 %0, %1;" : "=r"(u) : "f"(f));
    return u;
}

__device__ __forceinline__ void mma_tf32(float c[4],
                                         uint32_t a0, uint32_t a1, uint32_t a2, uint32_t a3,
                                         uint32_t b0, uint32_t b1) {
    asm volatile(
        "mma.sync.aligned.m16n8k8.row.col.f32.tf32.tf32.f32 "
        "{%0,%1,%2,%3}, {%4,%5,%6,%7}, {%8,%9}, {%0,%1,%2,%3};"
        : "+f"(c[0]), "+f"(c[1]), "+f"(c[2]), "+f"(c[3])
        : "r"(a0), "r"(a1), "r"(a2), "r"(a3), "r"(b0), "r"(b1));
}

__device__ __forceinline__ void cp_async16(void* smem_dst, const void* gmem_src) {
    uint32_t s = (uint32_t)__cvta_generic_to_shared(smem_dst);
    asm volatile("cp.async.cg.shared.global [%0], [%1], 16;" :: "r"(s), "l"(gmem_src));
}
__device__ __forceinline__ void cp_async_commit() {
    asm volatile("cp.async.commit_group;");
}
template <int N>
__device__ __forceinline__ void cp_async_wait() {
    asm volatile("cp.async.wait_group %0;" :: "n"(N));
}

// ---------------- TF32 GEMM core (shared by both kernels) ----------------
// C = A(M,K) * W(N,K)^T + bias ; cp.async double-buffered, BK=64.
#define BM 128
#define BN 128
#define BK 64
#define KPAD 68          // 68 floats = 272B row stride (16B-aligned, 4-bank skew)
#define TILE_F (BM * KPAD)
#define NTILES (DM / BK) // 16
#define GEMM_SMEM (4 * TILE_F * (int)sizeof(float))   // 139264 bytes

// permute=0: C row = m ; permute=1: C row = (m&4095)*8 + (m>>12)
__device__ __forceinline__ void gemm_core(
    const float* __restrict__ A, const float* __restrict__ W,
    const float* __restrict__ bias, float* __restrict__ C, int permute)
{
    extern __shared__ float smem[];
    float* sA = smem;                 // [2][BM][KPAD]
    float* sB = smem + 2 * TILE_F;    // [2][BN][KPAD]

    const int tid = threadIdx.x;
    const int m0 = blockIdx.y * BM;
    const int n0 = blockIdx.x * BN;
    const int w = tid >> 5, lane = tid & 31;
    const int wm = w & 1;        // 0..1 -> 64-row warp tile
    const int wn = w >> 1;       // 0..3 -> 32-col warp tile
    const int gid = lane >> 2, tq = lane & 3;

    float acc[4][4][4];
#pragma unroll
    for (int i = 0; i < 4; i++)
#pragma unroll
        for (int j = 0; j < 4; j++)
#pragma unroll
            for (int k = 0; k < 4; k++) acc[i][j][k] = 0.f;

    // ---- prefetch tile 0 ----
    {
#pragma unroll
        for (int i = 0; i < 8; i++) {
            int idx = i * 256 + tid;
            int r = idx >> 4;
            int c4 = (idx & 15) << 2;
            cp_async16(&sA[r * KPAD + c4], A + (size_t)(m0 + r) * DM + c4);
            cp_async16(&sB[r * KPAD + c4], W + (size_t)(n0 + r) * DM + c4);
        }
        cp_async_commit();
    }

    for (int t = 0; t < NTILES; t++) {
        if (t + 1 < NTILES) {
            const int k0 = (t + 1) * BK;
            float* dA = sA + ((t + 1) & 1) * TILE_F;
            float* dB = sB + ((t + 1) & 1) * TILE_F;
#pragma unroll
            for (int i = 0; i < 8; i++) {
                int idx = i * 256 + tid;
                int r = idx >> 4;
                int c4 = (idx & 15) << 2;
                cp_async16(&dA[r * KPAD + c4], A + (size_t)(m0 + r) * DM + k0 + c4);
                cp_async16(&dB[r * KPAD + c4], W + (size_t)(n0 + r) * DM + k0 + c4);
            }
            cp_async_commit();
            cp_async_wait<1>();
        } else {
            cp_async_wait<0>();
        }
        __syncthreads();

        const float* cA = sA + (t & 1) * TILE_F;
        const float* cB = sB + (t & 1) * TILE_F;

#pragma unroll
        for (int kk = 0; kk < BK; kk += 8) {
            uint32_t af[4][4], bf[4][2];
#pragma unroll
            for (int mi = 0; mi < 4; mi++) {
                int row = wm * 64 + mi * 16 + gid;
                af[mi][0] = f2tf32(cA[row * KPAD + kk + tq]);
                af[mi][1] = f2tf32(cA[(row + 8) * KPAD + kk + tq]);
                af[mi][2] = f2tf32(cA[row * KPAD + kk + tq + 4]);
                af[mi][3] = f2tf32(cA[(row + 8) * KPAD + kk + tq + 4]);
            }
#pragma unroll
            for (int ni = 0; ni < 4; ni++) {
                int col = wn * 32 + ni * 8 + gid;
                bf[ni][0] = f2tf32(cB[col * KPAD + kk + tq]);
                bf[ni][1] = f2tf32(cB[col * KPAD + kk + tq + 4]);
            }
#pragma unroll
            for (int mi = 0; mi < 4; mi++)
#pragma unroll
                for (int ni = 0; ni < 4; ni++)
                    mma_tf32(acc[mi][ni],
                             af[mi][0], af[mi][1], af[mi][2], af[mi][3],
                             bf[ni][0], bf[ni][1]);
        }
        __syncthreads();   // buffer (t&1) fully consumed before next prefetch
    }

    // epilogue: add bias, apply row permutation, store
#pragma unroll
    for (int mi = 0; mi < 4; mi++) {
#pragma unroll
        for (int ni = 0; ni < 4; ni++) {
            int row0 = m0 + wm * 64 + mi * 16 + gid;
            int row1 = row0 + 8;
            int col = n0 + wn * 32 + ni * 8 + tq * 2;
            float bb0 = bias[col], bb1 = bias[col + 1];
            size_t or0 = permute ? (size_t)((row0 & 4095) * 8 + (row0 >> 12)) : (size_t)row0;
            size_t or1 = permute ? (size_t)((row1 & 4095) * 8 + (row1 >> 12)) : (size_t)row1;
            C[or0 * DM + col]     = acc[mi][ni][0] + bb0;
            C[or0 * DM + col + 1] = acc[mi][ni][1] + bb1;
            C[or1 * DM + col]     = acc[mi][ni][2] + bb0;
            C[or1 * DM + col + 1] = acc[mi][ni][3] + bb1;
        }
    }
}

// QKV projections in ONE launch: blockIdx.z in {0,1,2} selects the stream.
// Eliminates 2 partial-wave boundaries (256 CTAs / 148 SMs = 73%-full wave 2
// per launch x3) plus inter-launch gaps.
__global__ __launch_bounds__(256, 1) void gemm_qkv(
    const float* __restrict__ Aq, const float* __restrict__ Ak,
    const float* __restrict__ Av,
    const float* __restrict__ Wq, const float* __restrict__ Wk,
    const float* __restrict__ Wv,
    const float* __restrict__ bq, const float* __restrict__ bk,
    const float* __restrict__ bv,
    float* __restrict__ Cq, float* __restrict__ Ck, float* __restrict__ Cv)
{
    const int z = blockIdx.z;
    const float* A = (z == 0) ? Aq : (z == 1) ? Ak : Av;
    const float* W = (z == 0) ? Wq : (z == 1) ? Wk : Wv;
    const float* b = (z == 0) ? bq : (z == 1) ? bk : bv;
    float*       C = (z == 0) ? Cq : (z == 1) ? Ck : Cv;
    gemm_core(A, W, b, C, 0);
}

__global__ __launch_bounds__(256, 1) void gemm_out(
    const float* __restrict__ A, const float* __restrict__ W,
    const float* __restrict__ bias, float* __restrict__ C)
{
    gemm_core(A, W, bias, C, 1);
}

// ---------------- per-position head-mixing attention + sparsemax ------------
// One block (256 thr) per (a,b) position. All smem traffic vectorized to
// float4 (round-3 ncu: L1 46.7% top pipe on scalar LDS — cut wavefronts ~4x).
#define APAD 68   // floats per row: float4-aligned

__global__ __launch_bounds__(256) void attn_kernel(
    const float* __restrict__ Q, const float* __restrict__ K,
    const float* __restrict__ V, float* __restrict__ X)
{
    const int pos = blockIdx.x;            // pos = a*BATCH + b
    const int a = pos >> 3, b = pos & 7;
    const int tid = threadIdx.x;

    __shared__ float Qs[NHEADS][APAD];
    __shared__ float Ks[NHEADS][APAD];
    __shared__ float Vs[NHEADS][APAD];
    __shared__ float Ss[NHEADS][NHEADS];
    __shared__ float At[NHEADS][NHEADS];

    // vectorized global load: 256 float4 per array, 1 per thread
    {
        const float4* q4 = (const float4*)(Q + (size_t)pos * DM);
        const float4* k4 = (const float4*)(K + (size_t)pos * DM);
        const float4* v4 = (const float4*)(V + (size_t)pos * DM);
        int hh = tid >> 4, dq = tid & 15;     // dq: float4 index within row
        *(float4*)&Qs[hh][dq * 4] = q4[tid];
        *(float4*)&Ks[hh][dq * 4] = k4[tid];
        *(float4*)&Vs[hh][dq * 4] = v4[tid];
    }
    __syncthreads();

    // scores: thread (h,g), dot over HD via float4 (16+16 LDS.128)
    {
        int h = tid >> 4, g = tid & 15;
        float s = 0.f;
#pragma unroll
        for (int d4 = 0; d4 < 16; d4++) {
            float4 qv = *(const float4*)&Qs[h][d4 * 4];
            float4 kv = *(const float4*)&Ks[g][d4 * 4];
            s += qv.x * kv.x + qv.y * kv.y + qv.z * kv.z + qv.w * kv.w;
        }
        Ss[h][g] = s * (1.0f / 12.0f);   // 1/(sqrt(64)*alpha)
    }
    __syncthreads();

    // sparsemax per head row (16 values) — threads 0..15
    if (tid < NHEADS) {
        float z[16], zs[16], cum[16];
#pragma unroll
        for (int g = 0; g < 16; g++) { z[g] = Ss[tid][g]; zs[g] = z[g]; }
        for (int i = 1; i < 16; i++) {        // insertion sort descending
            float key = zs[i];
            int j = i - 1;
            while (j >= 0 && zs[j] < key) { zs[j + 1] = zs[j]; j--; }
            zs[j + 1] = key;
        }
        float c = 0.f;
        int cnt = 0;
        for (int i = 0; i < 16; i++) {
            c += zs[i];
            cum[i] = c;
            if (zs[i] - (c - 1.0f) / (float)(i + 1) > 0.f) cnt++;
        }
        if (cnt < 1) cnt = 1;
        float tau = (cum[cnt - 1] - 1.0f) / (float)cnt;
#pragma unroll
        for (int g = 0; g < 16; g++) At[tid][g] = fmaxf(z[g] - tau, 0.f);
    }
    __syncthreads();

    // attn_out[h][d] = sum_g At[h][g] * V[g][d]; one float4 output per thread.
    // Per g-iteration: At broadcast; Vs reads = 16 distinct float4 x 16-way
    // broadcast -> conflict-free. Write: X[b][h*256 + a/16][(a%16)*64 + d].
    {
        int hh = tid >> 4, dq = tid & 15;
        float4 o = make_float4(0.f, 0.f, 0.f, 0.f);
#pragma unroll
        for (int g = 0; g < 16; g++) {
            float wgt = At[hh][g];
            float4 vv = *(const float4*)&Vs[g][dq * 4];
            o.x += wgt * vv.x; o.y += wgt * vv.y; o.z += wgt * vv.z; o.w += wgt * vv.w;
        }
        const size_t xbase = (size_t)b * SEQA * DM + (size_t)(a >> 4) * DM
                           + (size_t)(a & 15) * HD;
        *(float4*)&X[xbase + (size_t)hh * 256 * DM + dq * 4] = o;
    }
}

// ---------------- launch ----------------
extern "C" void kernel_launch(void* const* d_in, const int* in_sizes, int n_in,
                              void* d_out, int out_size)
{
    const float* query = (const float*)d_in[0];
    const float* key   = (const float*)d_in[1];
    const float* value = (const float*)d_in[2];
    const float* Wq = (const float*)d_in[3];
    const float* bq = (const float*)d_in[4];
    const float* Wk = (const float*)d_in[5];
    const float* bk = (const float*)d_in[6];
    const float* Wv = (const float*)d_in[7];
    const float* bv = (const float*)d_in[8];
    const float* Wo = (const float*)d_in[9];
    const float* bo = (const float*)d_in[10];
    float* out = (float*)d_out;

    float *pQ, *pK, *pV, *pX;
    cudaGetSymbolAddress((void**)&pQ, g_Q);
    cudaGetSymbolAddress((void**)&pK, g_K);
    cudaGetSymbolAddress((void**)&pV, g_V);
    cudaGetSymbolAddress((void**)&pX, g_X);

    cudaFuncSetAttribute(gemm_qkv, cudaFuncAttributeMaxDynamicSharedMemorySize,
                         GEMM_SMEM);
    cudaFuncSetAttribute(gemm_out, cudaFuncAttributeMaxDynamicSharedMemorySize,
                         GEMM_SMEM);

    dim3 gq(DM / BN, MROWS / BM, 3);   // (8, 256, 3) — QKV in one launch
    gemm_qkv<<<gq, 256, GEMM_SMEM>>>(query, key, value,
                                     Wq, Wk, Wv, bq, bk, bv,
                                     pQ, pK, pV);
    attn_kernel<<<MROWS, 256>>>(pQ, pK, pV, pX);
    dim3 go(DM / BN, MROWS / BM);      // (8, 256)
    gemm_out<<<go, 256, GEMM_SMEM>>>(pX, Wo, bo, out);
}